// round 4
// baseline (speedup 1.0000x reference)
#include <cuda_runtime.h>
#include <cstdint>

// Problem constants
#define B_SZ 4
#define T_LEN 2048
#define C_DIM 1024
#define H_N 16
#define D_H 64
#define M_ROWS 8192   // B*T

// Staging (tf32 bit patterns stored as u32)
__device__ uint32_t g_xc[M_ROWS * C_DIM];   // x, k-permuted
__device__ uint32_t g_wq[C_DIM * C_DIM];    // W^T, k-permuted
__device__ uint32_t g_wk[C_DIM * C_DIM];
__device__ uint32_t g_wv[C_DIM * C_DIM];
__device__ uint32_t g_wp[C_DIM * C_DIM];
__device__ uint32_t g_q[M_ROWS * C_DIM];    // head layout, unpermuted
__device__ uint32_t g_k[M_ROWS * C_DIM];
__device__ uint32_t g_v[M_ROWS * C_DIM];
__device__ uint32_t g_y[M_ROWS * C_DIM];    // head layout, k-permuted

__device__ __forceinline__ int head_idx(int m, int n) {
    return (((((m >> 11) << 4) + (n >> 6)) << 11 | (m & 2047)) << 6) + (n & 63);
}

__device__ __forceinline__ uint32_t f2tf32(float f) {
    uint32_t u;
    asm("cvt.rna.tf32.f32 %0, %1;" : "=r"(u) : "f"(f));
    return u;
}

#define MMA_TF32(C0,C1,C2,C3,A0,A1,A2,A3,B0,B1)                           \
    asm volatile("mma.sync.aligned.m16n8k8.row.col.f32.tf32.tf32.f32 "    \
        "{%0,%1,%2,%3},{%4,%5,%6,%7},{%8,%9},{%0,%1,%2,%3};"              \
        : "+f"(C0), "+f"(C1), "+f"(C2), "+f"(C3)                          \
        : "r"(A0), "r"(A1), "r"(A2), "r"(A3), "r"(B0), "r"(B1))

#define CP_ASYNC16(smem_u32, gptr)                                        \
    asm volatile("cp.async.ca.shared.global [%0], [%1], 16;"              \
        :: "r"(smem_u32), "l"(gptr))
#define CP_COMMIT()  asm volatile("cp.async.commit_group;")
#define CP_WAIT(N)   asm volatile("cp.async.wait_group %0;" :: "n"(N))

#define LOG2E_F 1.4426950408889634f

__device__ __forceinline__ float exp2_fast(float t) {
    t = fmaxf(t, -115.0f);
    const float MAGIC = 12582912.0f;   // 2^23 + 2^22
    float zf = t + MAGIC;
    int n = __float_as_int(zf) - 0x4B400000;
    float r = t - (zf - MAGIC);
    float p = 0.00133335581f;
    p = fmaf(p, r, 0.00961812911f);
    p = fmaf(p, r, 0.05550410866f);
    p = fmaf(p, r, 0.24022650696f);
    p = fmaf(p, r, 0.69314718056f);
    p = fmaf(p, r, 1.0f);
    return __int_as_float(__float_as_int(p) + (n << 23));
}

// ---------------------------------------------------------------------------
// Convert kernels (run once per launch, tiny)
// perm within 8-group: p = 2*(c&3) + ((c>>2)&1); inverse: c = (p>>1) + 4*(p&1)
// ---------------------------------------------------------------------------
__global__ __launch_bounds__(256)
void cvt_x_kernel(const float* __restrict__ x, uint32_t* __restrict__ out)
{
    const int gid = blockIdx.x * 256 + threadIdx.x;   // one 8-group per thread
    const float* src = x + (size_t)gid * 8;
    uint32_t o[8];
#pragma unroll
    for (int p = 0; p < 8; p++)
        o[p] = f2tf32(src[(p >> 1) + 4 * (p & 1)]);
    uint4* dst = (uint4*)(out + (size_t)gid * 8);
    dst[0] = make_uint4(o[0], o[1], o[2], o[3]);
    dst[1] = make_uint4(o[4], o[5], o[6], o[7]);
}

// W[k][n] -> Wt[n][k_perm], tf32. 32x32 tiles.
__global__ __launch_bounds__(256)
void cvt_wt_kernel(const float* __restrict__ W, uint32_t* __restrict__ Wt)
{
    __shared__ uint32_t tile[32][33];
    const int tx = threadIdx.x;         // 0..31
    const int ty = threadIdx.y;         // 0..7
    const int k0 = blockIdx.y * 32;
    const int n0 = blockIdx.x * 32;
#pragma unroll
    for (int r = 0; r < 4; r++)
        tile[ty + 8 * r][tx] = f2tf32(W[(k0 + ty + 8 * r) * C_DIM + n0 + tx]);
    __syncthreads();
    const int kp = (tx & 24) | (((tx & 3) << 1) | ((tx >> 2) & 1));
#pragma unroll
    for (int r = 0; r < 4; r++) {
        const int n = n0 + ty + 8 * r;
        Wt[n * C_DIM + k0 + kp] = tile[tx][ty + 8 * r];
    }
}

// ---------------------------------------------------------------------------
// TF32 GEMM, pre-converted operands. A: [m][k_perm] (flat or head layout),
// Wt: [n][k_perm]. BM=BN=128, BK=16, 256 thr, 8 warps (4m x 2n), 32x64/warp.
// Smem stride 24 -> all fragment loads are conflict-free LDS.64.
// ---------------------------------------------------------------------------
#define BK 16
#define SLD 24

template <bool A_HEAD, bool OUT_TF32_HEAD>
__global__ __launch_bounds__(256)
void gemm_tt(const uint32_t* __restrict__ A, const uint32_t* __restrict__ Wt,
             const float* __restrict__ bias, void* __restrict__ outv)
{
    __shared__ uint32_t As[2][128 * SLD];
    __shared__ uint32_t Bs[2][128 * SLD];

    const int bm = blockIdx.y * 128;
    const int bn = blockIdx.x * 128;
    const int tid = threadIdx.x;
    const int warp = tid >> 5;
    const int lane = tid & 31;
    const int g = lane >> 2;
    const int t = lane & 3;
    const int wm = (warp >> 1) * 32;
    const int wn = (warp & 1) * 64;

    const uint32_t asBase = (uint32_t)__cvta_generic_to_shared(&As[0][0]);
    const uint32_t bsBase = (uint32_t)__cvta_generic_to_shared(&Bs[0][0]);
    const uint32_t stageBytes = 128 * SLD * 4;

    float acc[2][8][4];
#pragma unroll
    for (int mt = 0; mt < 2; mt++)
#pragma unroll
        for (int nt = 0; nt < 8; nt++)
#pragma unroll
            for (int r = 0; r < 4; r++) acc[mt][nt][r] = 0.f;

    auto issue_stage = [&](int s, int k0) {
#pragma unroll
        for (int c = 0; c < 2; c++) {
            const int idx = tid + c * 256;
            const int r = idx >> 2;
            const int j4 = (idx & 3) << 2;
            const uint32_t* ga = A_HEAD ? A + head_idx(bm + r, k0 + j4)
                                        : A + (size_t)(bm + r) * C_DIM + k0 + j4;
            CP_ASYNC16(asBase + s * stageBytes + (r * SLD + j4) * 4, ga);
            const uint32_t* gb = Wt + (size_t)(bn + r) * C_DIM + k0 + j4;
            CP_ASYNC16(bsBase + s * stageBytes + (r * SLD + j4) * 4, gb);
        }
        CP_COMMIT();
    };

    issue_stage(0, 0);

    int stage = 0;
    for (int it = 0; it < C_DIM / BK; it++) {
        if (it + 1 < C_DIM / BK) {
            issue_stage(stage ^ 1, (it + 1) * BK);
            CP_WAIT(1);
        } else {
            CP_WAIT(0);
        }
        __syncthreads();

        const uint32_t* as = As[stage];
        const uint32_t* bs = Bs[stage];
#pragma unroll
        for (int kk8 = 0; kk8 < 2; kk8++) {
            const int kk = kk8 << 3;
            uint2 a02[2], a13[2];
#pragma unroll
            for (int mt = 0; mt < 2; mt++) {
                const int row = wm + mt * 16 + g;
                a02[mt] = *(const uint2*)&as[row * SLD + kk + 2 * t];
                a13[mt] = *(const uint2*)&as[(row + 8) * SLD + kk + 2 * t];
            }
#pragma unroll
            for (int nt = 0; nt < 8; nt++) {
                const uint2 b01 = *(const uint2*)&bs[(wn + nt * 8 + g) * SLD + kk + 2 * t];
                MMA_TF32(acc[0][nt][0], acc[0][nt][1], acc[0][nt][2], acc[0][nt][3],
                         a02[0].x, a13[0].x, a02[0].y, a13[0].y, b01.x, b01.y);
                MMA_TF32(acc[1][nt][0], acc[1][nt][1], acc[1][nt][2], acc[1][nt][3],
                         a02[1].x, a13[1].x, a02[1].y, a13[1].y, b01.x, b01.y);
            }
        }
        __syncthreads();
        stage ^= 1;
    }

#pragma unroll
    for (int mt = 0; mt < 2; mt++) {
#pragma unroll
        for (int nt = 0; nt < 8; nt++) {
            const int n = bn + wn + nt * 8 + t * 2;
            const float b0 = bias[n], b1 = bias[n + 1];
            const int m0 = bm + wm + mt * 16 + g;
            const int m1 = m0 + 8;
            if (OUT_TF32_HEAD) {
                uint32_t* out = (uint32_t*)outv;
                uint2 v0, v1;
                v0.x = f2tf32(acc[mt][nt][0] + b0); v0.y = f2tf32(acc[mt][nt][1] + b1);
                v1.x = f2tf32(acc[mt][nt][2] + b0); v1.y = f2tf32(acc[mt][nt][3] + b1);
                *(uint2*)(out + head_idx(m0, n)) = v0;
                *(uint2*)(out + head_idx(m1, n)) = v1;
            } else {
                float* out = (float*)outv;
                float2 v0, v1;
                v0.x = acc[mt][nt][0] + b0; v0.y = acc[mt][nt][1] + b1;
                v1.x = acc[mt][nt][2] + b0; v1.y = acc[mt][nt][3] + b1;
                *(float2*)(out + (size_t)m0 * C_DIM + n) = v0;
                *(float2*)(out + (size_t)m1 * C_DIM + n) = v1;
            }
        }
    }
}

// ---------------------------------------------------------------------------
// Flash attention, tf32 tensor cores, pre-converted u32 inputs.
// Block = 128 threads (4 warps), Br=Bc=64, D=64.
// Writes y as tf32 u32 in the k-permuted head layout for the final GEMM.
// ---------------------------------------------------------------------------
#define ALD 68
#define VLD 72
#define OFF_Q 0
#define OFF_K (64 * ALD)
#define OFF_V (2 * 64 * ALD)
#define OFF_P (2 * 64 * ALD + 64 * VLD)
#define ATTN_U32 (3 * 64 * ALD + 64 * VLD)

__global__ __launch_bounds__(128)
void attn_tc(const uint32_t* __restrict__ Q, const uint32_t* __restrict__ K,
             const uint32_t* __restrict__ V, uint32_t* __restrict__ Y)
{
    extern __shared__ uint32_t su[];
    uint32_t* Qs = su + OFF_Q;
    uint32_t* Ks = su + OFF_K;
    uint32_t* Vs = su + OFF_V;
    uint32_t* Ps = su + OFF_P;

    const int bh = blockIdx.y;
    const int qb = blockIdx.x;
    const int q0 = qb << 6;
    const uint32_t* Qp = Q + (((size_t)bh << 11) + q0) * 64;
    const uint32_t* Kp = K + ((size_t)bh << 11) * 64;
    const uint32_t* Vp = V + ((size_t)bh << 11) * 64;

    const int tid  = threadIdx.x;
    const int warp = tid >> 5;
    const int lane = tid & 31;
    const int g    = lane >> 2;
    const int t    = lane & 3;
    const int m0   = warp << 4;

    for (int i = tid; i < 1024; i += 128) {
        const int r = i >> 4, c = (i & 15) << 2;
        *(uint4*)&Qs[r * ALD + c] = *(const uint4*)(Qp + (r << 6) + c);
    }

    float oacc[8][4];
#pragma unroll
    for (int nf = 0; nf < 8; nf++)
#pragma unroll
        for (int r = 0; r < 4; r++) oacc[nf][r] = 0.f;
    float mrow0 = -1e30f, mrow1 = -1e30f, lrow0 = 0.f, lrow1 = 0.f;

    const float C1 = 0.125f * LOG2E_F;

    for (int kt = 0; kt <= qb; kt++) {
        __syncthreads();
        const uint32_t* kb = Kp + (kt << 12);
        const uint32_t* vb = Vp + (kt << 12);
        for (int i = tid; i < 1024; i += 128) {
            const int r = i >> 4, c = (i & 15) << 2;
            *(uint4*)&Ks[r * ALD + c] = *(const uint4*)(kb + (r << 6) + c);
            *(uint4*)&Vs[r * VLD + c] = *(const uint4*)(vb + (r << 6) + c);
        }
        __syncthreads();

        float sacc[8][4];
#pragma unroll
        for (int nf = 0; nf < 8; nf++)
#pragma unroll
            for (int r = 0; r < 4; r++) sacc[nf][r] = 0.f;

#pragma unroll
        for (int kk8 = 0; kk8 < 8; kk8++) {
            const int kk = kk8 << 3;
            const uint32_t a0 = Qs[(m0 + g) * ALD + kk + t];
            const uint32_t a1 = Qs[(m0 + g + 8) * ALD + kk + t];
            const uint32_t a2 = Qs[(m0 + g) * ALD + kk + t + 4];
            const uint32_t a3 = Qs[(m0 + g + 8) * ALD + kk + t + 4];
#pragma unroll
            for (int nf = 0; nf < 8; nf++) {
                const uint32_t b0 = Ks[(nf * 8 + g) * ALD + kk + t];
                const uint32_t b1 = Ks[(nf * 8 + g) * ALD + kk + t + 4];
                MMA_TF32(sacc[nf][0], sacc[nf][1], sacc[nf][2], sacc[nf][3],
                         a0, a1, a2, a3, b0, b1);
            }
        }

        if (kt == qb) {
#pragma unroll
            for (int nf = 0; nf < 8; nf++) {
                const int c = nf * 8 + 2 * t;
                if (c     > m0 + g)     sacc[nf][0] = -1e30f;
                if (c + 1 > m0 + g)     sacc[nf][1] = -1e30f;
                if (c     > m0 + g + 8) sacc[nf][2] = -1e30f;
                if (c + 1 > m0 + g + 8) sacc[nf][3] = -1e30f;
            }
        }

        float mx0 = -1e30f, mx1 = -1e30f;
#pragma unroll
        for (int nf = 0; nf < 8; nf++) {
            mx0 = fmaxf(mx0, fmaxf(sacc[nf][0], sacc[nf][1]));
            mx1 = fmaxf(mx1, fmaxf(sacc[nf][2], sacc[nf][3]));
        }
        mx0 = fmaxf(mx0, __shfl_xor_sync(0xffffffffu, mx0, 1));
        mx0 = fmaxf(mx0, __shfl_xor_sync(0xffffffffu, mx0, 2));
        mx1 = fmaxf(mx1, __shfl_xor_sync(0xffffffffu, mx1, 1));
        mx1 = fmaxf(mx1, __shfl_xor_sync(0xffffffffu, mx1, 2));
        mx0 *= 0.125f; mx1 *= 0.125f;

        const float mn0 = fmaxf(mrow0, mx0);
        const float mn1 = fmaxf(mrow1, mx1);
        const float al0 = exp2_fast((mrow0 - mn0) * LOG2E_F);
        const float al1 = exp2_fast((mrow1 - mn1) * LOG2E_F);
        mrow0 = mn0; mrow1 = mn1;
        const float base0 = -mn0 * LOG2E_F;
        const float base1 = -mn1 * LOG2E_F;

        float sum0 = 0.f, sum1 = 0.f;
#pragma unroll
        for (int nf = 0; nf < 8; nf++) {
            const float p0 = exp2_fast(fmaf(sacc[nf][0], C1, base0));
            const float p1 = exp2_fast(fmaf(sacc[nf][1], C1, base0));
            const float p2 = exp2_fast(fmaf(sacc[nf][2], C1, base1));
            const float p3 = exp2_fast(fmaf(sacc[nf][3], C1, base1));
            sum0 += p0 + p1;
            sum1 += p2 + p3;
            uint2 u01; u01.x = f2tf32(p0); u01.y = f2tf32(p1);
            uint2 u23; u23.x = f2tf32(p2); u23.y = f2tf32(p3);
            *(uint2*)&Ps[(m0 + g) * ALD + nf * 8 + 2 * t] = u01;
            *(uint2*)&Ps[(m0 + g + 8) * ALD + nf * 8 + 2 * t] = u23;
            oacc[nf][0] *= al0; oacc[nf][1] *= al0;
            oacc[nf][2] *= al1; oacc[nf][3] *= al1;
        }
        sum0 += __shfl_xor_sync(0xffffffffu, sum0, 1);
        sum0 += __shfl_xor_sync(0xffffffffu, sum0, 2);
        sum1 += __shfl_xor_sync(0xffffffffu, sum1, 1);
        sum1 += __shfl_xor_sync(0xffffffffu, sum1, 2);
        lrow0 = lrow0 * al0 + sum0;
        lrow1 = lrow1 * al1 + sum1;

        __syncwarp();

#pragma unroll
        for (int kk8 = 0; kk8 < 8; kk8++) {
            const int kk = kk8 << 3;
            const uint32_t pa0 = Ps[(m0 + g) * ALD + kk + t];
            const uint32_t pa1 = Ps[(m0 + g + 8) * ALD + kk + t];
            const uint32_t pa2 = Ps[(m0 + g) * ALD + kk + t + 4];
            const uint32_t pa3 = Ps[(m0 + g + 8) * ALD + kk + t + 4];
#pragma unroll
            for (int nf = 0; nf < 8; nf++) {
                const uint32_t vb0 = Vs[(kk + t) * VLD + nf * 8 + g];
                const uint32_t vb1 = Vs[(kk + t + 4) * VLD + nf * 8 + g];
                MMA_TF32(oacc[nf][0], oacc[nf][1], oacc[nf][2], oacc[nf][3],
                         pa0, pa1, pa2, pa3, vb0, vb1);
            }
        }
    }

    // normalize + store y as tf32 u32 in k-permuted head layout
    const float inv0 = 1.f / lrow0;
    const float inv1 = 1.f / lrow1;
    uint32_t* yp = Y + (((size_t)bh << 11) + q0) * 64;
    const int cc = 2 * t;
    const int p0 = ((cc & 3) << 1) | ((cc >> 2) & 1);
    const int p1 = (((cc + 1) & 3) << 1) | (((cc + 1) >> 2) & 1);
#pragma unroll
    for (int nf = 0; nf < 8; nf++) {
        const int cb = nf * 8;
        yp[(m0 + g) * 64 + cb + p0]     = f2tf32(oacc[nf][0] * inv0);
        yp[(m0 + g) * 64 + cb + p1]     = f2tf32(oacc[nf][1] * inv0);
        yp[(m0 + g + 8) * 64 + cb + p0] = f2tf32(oacc[nf][2] * inv1);
        yp[(m0 + g + 8) * 64 + cb + p1] = f2tf32(oacc[nf][3] * inv1);
    }
}

// ---------------------------------------------------------------------------
extern "C" void kernel_launch(void* const* d_in, const int* in_sizes, int n_in,
                              void* d_out, int out_size)
{
    const float* x  = (const float*)d_in[0];
    const float* Wq = (const float*)d_in[1];
    const float* bq = (const float*)d_in[2];
    const float* Wk = (const float*)d_in[3];
    const float* bk = (const float*)d_in[4];
    const float* Wv = (const float*)d_in[5];
    const float* bv = (const float*)d_in[6];
    const float* Wp = (const float*)d_in[7];
    const float* bp = (const float*)d_in[8];
    float* out = (float*)d_out;

    uint32_t *xc, *wq, *wk, *wv, *wp, *q, *k, *v, *y;
    cudaGetSymbolAddress((void**)&xc, g_xc);
    cudaGetSymbolAddress((void**)&wq, g_wq);
    cudaGetSymbolAddress((void**)&wk, g_wk);
    cudaGetSymbolAddress((void**)&wv, g_wv);
    cudaGetSymbolAddress((void**)&wp, g_wp);
    cudaGetSymbolAddress((void**)&q, g_q);
    cudaGetSymbolAddress((void**)&k, g_k);
    cudaGetSymbolAddress((void**)&v, g_v);
    cudaGetSymbolAddress((void**)&y, g_y);

    // Stage conversions
    cvt_x_kernel<<<M_ROWS * C_DIM / 8 / 256, 256>>>(x, xc);
    const dim3 wtg(C_DIM / 32, C_DIM / 32);
    const dim3 wtb(32, 8);
    cvt_wt_kernel<<<wtg, wtb>>>(Wq, wq);
    cvt_wt_kernel<<<wtg, wtb>>>(Wk, wk);
    cvt_wt_kernel<<<wtg, wtb>>>(Wv, wv);
    cvt_wt_kernel<<<wtg, wtb>>>(Wp, wp);

    const dim3 gg(C_DIM / 128, M_ROWS / 128);   // (8, 64)
    gemm_tt<false, true><<<gg, 256>>>(xc, wq, bq, q);
    gemm_tt<false, true><<<gg, 256>>>(xc, wk, bk, k);
    gemm_tt<false, true><<<gg, 256>>>(xc, wv, bv, v);

    const int attn_smem = ATTN_U32 * (int)sizeof(uint32_t);
    cudaFuncSetAttribute(attn_tc, cudaFuncAttributeMaxDynamicSharedMemorySize,
                         attn_smem);
    const dim3 ga(T_LEN / 64, B_SZ * H_N);      // (32, 64)
    attn_tc<<<ga, 128, attn_smem>>>(q, k, v, y);

    gemm_tt<true, false><<<gg, 256>>>(y, wp, bp, out);
}